// round 3
// baseline (speedup 1.0000x reference)
#include <cuda_runtime.h>

// Problem constants
constexpr int BG      = 4;        // B*G
constexpr int SEQ     = 1024;     // QLEN = KVLEN
constexpr int CH      = 1024;     // DIN = QK_CH = V_CH = OUT_CH
constexpr int HEADS   = 16;
constexpr int HDIM    = 64;       // per-head dim
constexpr int ROWS    = BG * SEQ; // 4096
constexpr long long BG_STRIDE = (long long)SEQ * CH;        // 1048576
constexpr long long PROB_BATCH = (long long)SEQ * SEQ;      // 1048576 per (b,g,h)

// Scratch (allocation-free rule: __device__ globals)
__device__ float g_Q[ROWS * CH];
__device__ float g_K[ROWS * CH];
__device__ float g_V[ROWS * CH];
__device__ float g_C[ROWS * CH];

// ---------------------------------------------------------------------------
// Generic register-tiled SGEMM.
//   BTRANS=true : C[m,n] = scale * sum_k A[m,k] * B[n,k]   (B is [N,K] row-major)
//   BTRANS=false: C[m,n] = scale * sum_k A[m,k] * B[k,n]   (B is [K,N] row-major)
// Batched via grid.z with split batch index: off = (z/HB)*s1 + (z%HB)*s2.
// All M,N multiples of BM,BN; K multiple of BK; pointers 16B aligned per call.
// ---------------------------------------------------------------------------
template<int BM, int BN, int BK, int TM, int TN, bool BTRANS>
__global__ __launch_bounds__((BM / TM) * (BN / TN), 2)
void gemm_kernel(const float* __restrict__ A, const float* __restrict__ Bm,
                 float* __restrict__ C, const float* __restrict__ bias,
                 int K, int lda, int ldb, int ldc,
                 int HB,
                 long long as1, long long as2,
                 long long bs1, long long bs2,
                 long long cs1, long long cs2,
                 float scale)
{
    constexpr int NT = (BM / TM) * (BN / TN);

    const int z  = blockIdx.z;
    const int zo = z / HB;
    const int zi = z % HB;
    A  += zo * as1 + zi * as2;
    Bm += zo * bs1 + zi * bs2;
    C  += zo * cs1 + zi * cs2;

    __shared__ float As[BK][BM + 4];
    __shared__ float Bs[BK][BN + 4];

    const int tid  = threadIdx.x;
    const int row0 = blockIdx.y * BM;
    const int col0 = blockIdx.x * BN;
    const int tcol = (tid % (BN / TN)) * TN;
    const int trow = (tid / (BN / TN)) * TM;

    float acc[TM][TN];
    #pragma unroll
    for (int i = 0; i < TM; i++)
        #pragma unroll
        for (int j = 0; j < TN; j++)
            acc[i][j] = 0.0f;

    for (int k0 = 0; k0 < K; k0 += BK) {
        // ---- load A tile (BM x BK), float4 along K, store transposed ----
        {
            constexpr int TPR  = BK / 4;       // threads per row
            constexpr int STEP = NT / TPR;     // rows per iteration
            const int r = tid / TPR;
            const int c = (tid % TPR) * 4;
            #pragma unroll
            for (int rr = r; rr < BM; rr += STEP) {
                float4 v = *reinterpret_cast<const float4*>(
                    A + (long long)(row0 + rr) * lda + k0 + c);
                As[c + 0][rr] = v.x;
                As[c + 1][rr] = v.y;
                As[c + 2][rr] = v.z;
                As[c + 3][rr] = v.w;
            }
        }
        // ---- load B tile ----
        if constexpr (BTRANS) {
            constexpr int TPR  = BK / 4;
            constexpr int STEP = NT / TPR;
            const int r = tid / TPR;
            const int c = (tid % TPR) * 4;
            #pragma unroll
            for (int rr = r; rr < BN; rr += STEP) {
                float4 v = *reinterpret_cast<const float4*>(
                    Bm + (long long)(col0 + rr) * ldb + k0 + c);
                Bs[c + 0][rr] = v.x;
                Bs[c + 1][rr] = v.y;
                Bs[c + 2][rr] = v.z;
                Bs[c + 3][rr] = v.w;
            }
        } else {
            constexpr int TPR  = BN / 4;
            constexpr int STEP = NT / TPR;
            const int r = tid / TPR;
            const int c = (tid % TPR) * 4;
            #pragma unroll
            for (int rr = r; rr < BK; rr += STEP) {
                float4 v = *reinterpret_cast<const float4*>(
                    Bm + (long long)(k0 + rr) * ldb + col0 + c);
                *reinterpret_cast<float4*>(&Bs[rr][c]) = v;
            }
        }
        __syncthreads();

        // ---- FMA on the tile ----
        #pragma unroll
        for (int kk = 0; kk < BK; kk++) {
            float ra[TM], rb[TN];
            #pragma unroll
            for (int i = 0; i < TM; i++) ra[i] = As[kk][trow + i];
            #pragma unroll
            for (int j = 0; j < TN; j++) rb[j] = Bs[kk][tcol + j];
            #pragma unroll
            for (int i = 0; i < TM; i++)
                #pragma unroll
                for (int j = 0; j < TN; j++)
                    acc[i][j] += ra[i] * rb[j];
        }
        __syncthreads();
    }

    // ---- epilogue: scale + optional bias, float4 stores ----
    float bv[TN];
    #pragma unroll
    for (int j = 0; j < TN; j++)
        bv[j] = bias ? bias[col0 + tcol + j] : 0.0f;

    #pragma unroll
    for (int i = 0; i < TM; i++) {
        float* crow = C + (long long)(row0 + trow + i) * ldc + col0 + tcol;
        #pragma unroll
        for (int j = 0; j < TN; j += 4) {
            float4 v;
            v.x = acc[i][j + 0] * scale + bv[j + 0];
            v.y = acc[i][j + 1] * scale + bv[j + 1];
            v.z = acc[i][j + 2] * scale + bv[j + 2];
            v.w = acc[i][j + 3] * scale + bv[j + 3];
            *reinterpret_cast<float4*>(crow + j) = v;
        }
    }
}

// ---------------------------------------------------------------------------
// Row softmax in place: one block per row of 1024 floats, 256 threads.
// ---------------------------------------------------------------------------
__global__ __launch_bounds__(256)
void softmax_kernel(float* __restrict__ P)
{
    float* row = P + (long long)blockIdx.x * 1024;
    const int tid = threadIdx.x;

    float v[4];
    float mx = -1e30f;
    #pragma unroll
    for (int i = 0; i < 4; i++) {
        v[i] = row[tid + 256 * i];
        mx = fmaxf(mx, v[i]);
    }

    __shared__ float red[256];
    red[tid] = mx;
    __syncthreads();
    #pragma unroll
    for (int s = 128; s > 0; s >>= 1) {
        if (tid < s) red[tid] = fmaxf(red[tid], red[tid + s]);
        __syncthreads();
    }
    mx = red[0];
    __syncthreads();

    float sum = 0.0f;
    #pragma unroll
    for (int i = 0; i < 4; i++) {
        v[i] = __expf(v[i] - mx);
        sum += v[i];
    }
    red[tid] = sum;
    __syncthreads();
    #pragma unroll
    for (int s = 128; s > 0; s >>= 1) {
        if (tid < s) red[tid] += red[tid + s];
        __syncthreads();
    }
    const float inv = 1.0f / red[0];

    #pragma unroll
    for (int i = 0; i < 4; i++)
        row[tid + 256 * i] = v[i] * inv;
}

// ---------------------------------------------------------------------------
// Launch
// ---------------------------------------------------------------------------
extern "C" void kernel_launch(void* const* d_in, const int* in_sizes, int n_in,
                              void* d_out, int out_size)
{
    const float* xq  = (const float*)d_in[0];
    const float* xkv = (const float*)d_in[1];
    const float* Wq  = (const float*)d_in[2];
    const float* bq  = (const float*)d_in[3];
    const float* Wk  = (const float*)d_in[4];
    const float* bk  = (const float*)d_in[5];
    const float* Wv  = (const float*)d_in[6];
    const float* bv  = (const float*)d_in[7];
    const float* Wo  = (const float*)d_in[8];
    const float* bo  = (const float*)d_in[9];

    float* out   = (float*)d_out;
    float* probs = out + (long long)ROWS * CH;   // out (4,194,304 f32) then probs

    float *Qp, *Kp, *Vp, *Cp;
    cudaGetSymbolAddress((void**)&Qp, g_Q);
    cudaGetSymbolAddress((void**)&Kp, g_K);
    cudaGetSymbolAddress((void**)&Vp, g_V);
    cudaGetSymbolAddress((void**)&Cp, g_C);

    // 1-3. Projections: [4096,1024] = X[4096,1024] @ W^T[1024,1024] + b
    dim3 projGrid(CH / 128, ROWS / 128, 1);
    gemm_kernel<128, 128, 16, 8, 8, true><<<projGrid, 256>>>(
        xq,  Wq, Qp, bq, CH, CH, CH, CH, 1, 0, 0, 0, 0, 0, 0, 1.0f);
    gemm_kernel<128, 128, 16, 8, 8, true><<<projGrid, 256>>>(
        xkv, Wk, Kp, bk, CH, CH, CH, CH, 1, 0, 0, 0, 0, 0, 0, 1.0f);
    gemm_kernel<128, 128, 16, 8, 8, true><<<projGrid, 256>>>(
        xkv, Wv, Vp, bv, CH, CH, CH, CH, 1, 0, 0, 0, 0, 0, 0, 1.0f);

    // 4. Scores: per (bg,h): S[n,m] = (1/8) * q[n,:] . k[m,:], K=64
    //    batch z = bg*16 + h ; A,B offset = bg*BG_STRIDE + h*64 ; C offset = z*1M
    dim3 scoreGrid(SEQ / 128, SEQ / 128, BG * HEADS);
    gemm_kernel<128, 128, 16, 8, 8, true><<<scoreGrid, 256>>>(
        Qp, Kp, probs, nullptr, HDIM, CH, CH, SEQ,
        HEADS, BG_STRIDE, HDIM, BG_STRIDE, HDIM,
        (long long)HEADS * PROB_BATCH, PROB_BATCH, 0.125f);

    // 5. Softmax rows (64 batches * 1024 rows)
    softmax_kernel<<<BG * HEADS * SEQ, 256>>>(probs);

    // 6. PV: per (bg,h): Ctx[n,d] = sum_m P[n,m] * V[m, h*64+d]  (B not transposed)
    dim3 pvGrid(HDIM / 64, SEQ / 128, BG * HEADS);
    gemm_kernel<128, 64, 16, 8, 4, false><<<pvGrid, 256>>>(
        probs, Vp, Cp, nullptr, SEQ, SEQ, CH, CH,
        HEADS, (long long)HEADS * PROB_BATCH, PROB_BATCH,
        BG_STRIDE, HDIM, BG_STRIDE, HDIM, 1.0f);

    // 7. Output projection: out = Ctx @ Wo^T + bo
    gemm_kernel<128, 128, 16, 8, 8, true><<<projGrid, 256>>>(
        Cp, Wo, out, bo, CH, CH, CH, CH, 1, 0, 0, 0, 0, 0, 0, 1.0f);
}

// round 5
// speedup vs baseline: 1.8051x; 1.8051x over previous
#include <cuda_runtime.h>
#include <cuda_bf16.h>
#include <cstdint>

// Problem constants
constexpr int BG      = 4;
constexpr int SEQ     = 1024;
constexpr int CH      = 1024;
constexpr int HEADS   = 16;
constexpr int HDIM    = 64;
constexpr int ROWS    = BG * SEQ;
constexpr long long BG_STRIDE  = (long long)SEQ * CH;
constexpr long long PROB_BATCH = (long long)SEQ * SEQ;

// Scratch (allocation-free rule: __device__ globals)
__device__ float g_Q[ROWS * CH];
__device__ float g_K[ROWS * CH];
__device__ float g_V[ROWS * CH];
__device__ float g_C[ROWS * CH];

// ---------------------------------------------------------------------------
// helpers
// ---------------------------------------------------------------------------
__device__ __forceinline__ uint32_t pack2(unsigned short lo, unsigned short hi) {
    return (uint32_t)lo | ((uint32_t)hi << 16);
}
__device__ __forceinline__ void bsplit(float x, unsigned short& h, unsigned short& l) {
    __nv_bfloat16 hb = __float2bfloat16_rn(x);
    h = __bfloat16_as_ushort(hb);
    l = __bfloat16_as_ushort(__float2bfloat16_rn(x - __bfloat162float(hb)));
}
__device__ __forceinline__ void ldmx4(uint32_t& r0, uint32_t& r1, uint32_t& r2, uint32_t& r3, uint32_t a) {
    asm volatile("ldmatrix.sync.aligned.m8n8.x4.shared.b16 {%0,%1,%2,%3},[%4];"
                 : "=r"(r0), "=r"(r1), "=r"(r2), "=r"(r3) : "r"(a));
}
__device__ __forceinline__ void ldmx4t(uint32_t& r0, uint32_t& r1, uint32_t& r2, uint32_t& r3, uint32_t a) {
    asm volatile("ldmatrix.sync.aligned.m8n8.x4.trans.shared.b16 {%0,%1,%2,%3},[%4];"
                 : "=r"(r0), "=r"(r1), "=r"(r2), "=r"(r3) : "r"(a));
}
__device__ __forceinline__ void mma16816(float* c, uint32_t a0, uint32_t a1, uint32_t a2, uint32_t a3,
                                         uint32_t b0, uint32_t b1) {
    asm volatile(
        "mma.sync.aligned.m16n8k16.row.col.f32.bf16.bf16.f32 "
        "{%0,%1,%2,%3},{%4,%5,%6,%7},{%8,%9},{%0,%1,%2,%3};"
        : "+f"(c[0]), "+f"(c[1]), "+f"(c[2]), "+f"(c[3])
        : "r"(a0), "r"(a1), "r"(a2), "r"(a3), "r"(b0), "r"(b1));
}

// ---------------------------------------------------------------------------
// Compensated-bf16 tensor-core GEMM.
//   BTRANS=true : C[m,n] = scale * sum_k A[m,k] * B[n,k]   (B [N,K] row-major)
//   BTRANS=false: C[m,n] = scale * sum_k A[m,k] * B[k,n]   (B [K,N] row-major)
// Each fp32 k-slot expands to 3 bf16 slots: A'=[ah,al,ah], B'=[bh,bh,bl]
// so one bf16 mma sweep computes ah*bh + al*bh + ah*bl (fp32 accumulate).
// 256 threads, 8 warps (4x2), warp tile 32 x BN/2. BM=128.
// ---------------------------------------------------------------------------
template<int BM, int BN, bool BTRANS, bool HASBIAS>
__global__ __launch_bounds__(256)
void mma_gemm(const float* __restrict__ A, const float* __restrict__ B,
              float* __restrict__ C, const float* __restrict__ bias,
              int K, int lda, int ldb, int ldc, int HB,
              long long as1, long long as2, long long bs1, long long bs2,
              long long cs1, long long cs2, float scale)
{
    constexpr int BKF   = 16;                 // fp32 K per tile -> 48 bf16
    constexpr int ASTR  = 56;                 // 112B rows = 7 x 16B (conflict-free ldmatrix)
    constexpr int BROWS = BTRANS ? BN : 48;
    constexpr int BSTR  = BTRANS ? 56 : 136;  // 272B = 17 x 16B
    constexpr int NLA   = BM / 64;            // float4 loads per thread (A)
    constexpr int NLB   = BTRANS ? BN / 64 : (BKF * BN) / 1024;
    constexpr int WTN   = BN / 2;
    constexpr int MT    = 2;
    constexpr int NT    = WTN / 8;
    constexpr int ASZ   = BM * ASTR;
    constexpr int BSZ   = BROWS * BSTR;

    extern __shared__ __nv_bfloat16 smem[];
    __nv_bfloat16* sA = smem;              // [2][ASZ]
    __nv_bfloat16* sB = smem + 2 * ASZ;    // [2][BSZ]

    const int tid = threadIdx.x, lane = tid & 31, warp = tid >> 5;
    const int wm = warp >> 1, wn = warp & 1;
    const int z = blockIdx.z, zo = z / HB, zi = z % HB;
    A += zo * as1 + zi * as2;
    B += zo * bs1 + zi * bs2;
    C += zo * cs1 + zi * cs2;
    const int row0 = blockIdx.y * BM, col0 = blockIdx.x * BN;

    float4 aldg[NLA], bldg[NLB];

    auto loadG = [&](int k0) {
        #pragma unroll
        for (int i = 0; i < NLA; i++) {
            int gi = tid + i * 256, r = gi >> 2, c = (gi & 3) << 2;
            aldg[i] = *reinterpret_cast<const float4*>(A + (long long)(row0 + r) * lda + k0 + c);
        }
        #pragma unroll
        for (int i = 0; i < NLB; i++) {
            int gi = tid + i * 256;
            if constexpr (BTRANS) {
                int r = gi >> 2, c = (gi & 3) << 2;
                bldg[i] = *reinterpret_cast<const float4*>(B + (long long)(col0 + r) * ldb + k0 + c);
            } else {
                int r = gi / (BN / 4), c = (gi % (BN / 4)) << 2;
                bldg[i] = *reinterpret_cast<const float4*>(B + (long long)(k0 + r) * ldb + col0 + c);
            }
        }
    };

    auto storeS = [&](int buf) {
        uint32_t* swA = reinterpret_cast<uint32_t*>(sA + buf * ASZ);
        #pragma unroll
        for (int i = 0; i < NLA; i++) {
            int gi = tid + i * 256, r = gi >> 2, c = (gi & 3) << 2;
            unsigned short h0, l0, h1, l1, h2, l2, h3, l3;
            bsplit(aldg[i].x, h0, l0); bsplit(aldg[i].y, h1, l1);
            bsplit(aldg[i].z, h2, l2); bsplit(aldg[i].w, h3, l3);
            uint32_t base = (uint32_t)(r * ASTR + 3 * c) >> 1;
            swA[base + 0] = pack2(h0, l0); swA[base + 1] = pack2(h0, h1); swA[base + 2] = pack2(l1, h1);
            swA[base + 3] = pack2(h2, l2); swA[base + 4] = pack2(h2, h3); swA[base + 5] = pack2(l3, h3);
        }
        uint32_t* swB = reinterpret_cast<uint32_t*>(sB + buf * BSZ);
        #pragma unroll
        for (int i = 0; i < NLB; i++) {
            int gi = tid + i * 256;
            unsigned short h0, l0, h1, l1, h2, l2, h3, l3;
            bsplit(bldg[i].x, h0, l0); bsplit(bldg[i].y, h1, l1);
            bsplit(bldg[i].z, h2, l2); bsplit(bldg[i].w, h3, l3);
            if constexpr (BTRANS) {
                int r = gi >> 2, c = (gi & 3) << 2;
                uint32_t base = (uint32_t)(r * BSTR + 3 * c) >> 1;
                swB[base + 0] = pack2(h0, h0); swB[base + 1] = pack2(l0, h1); swB[base + 2] = pack2(h1, l1);
                swB[base + 3] = pack2(h2, h2); swB[base + 4] = pack2(l2, h3); swB[base + 5] = pack2(h3, l3);
            } else {
                int r = gi / (BN / 4), c = (gi % (BN / 4)) << 2;
                uint32_t b0 = (uint32_t)((3 * r + 0) * BSTR + c) >> 1;
                uint32_t b1 = (uint32_t)((3 * r + 1) * BSTR + c) >> 1;
                uint32_t b2 = (uint32_t)((3 * r + 2) * BSTR + c) >> 1;
                uint32_t hi01 = pack2(h0, h1), hi23 = pack2(h2, h3);
                swB[b0] = hi01; swB[b0 + 1] = hi23;
                swB[b1] = hi01; swB[b1 + 1] = hi23;
                swB[b2] = pack2(l0, l1); swB[b2 + 1] = pack2(l2, l3);
            }
        }
    };

    float acc[MT][NT][4];
    #pragma unroll
    for (int mt = 0; mt < MT; mt++)
        #pragma unroll
        for (int nt = 0; nt < NT; nt++)
            #pragma unroll
            for (int i = 0; i < 4; i++)
                acc[mt][nt][i] = 0.0f;

    auto compute = [&](int buf) {
        uint32_t aB = (uint32_t)__cvta_generic_to_shared(sA + buf * ASZ);
        uint32_t bB = (uint32_t)__cvta_generic_to_shared(sB + buf * BSZ);
        #pragma unroll
        for (int ks = 0; ks < 3; ks++) {
            uint32_t af[MT][4];
            #pragma unroll
            for (int mt = 0; mt < MT; mt++) {
                int r = wm * 32 + mt * 16 + (lane & 15);
                int c = ks * 16 + ((lane >> 4) << 3);
                ldmx4(af[mt][0], af[mt][1], af[mt][2], af[mt][3],
                      aB + (uint32_t)(r * ASTR + c) * 2);
            }
            uint32_t bf[NT][2];
            #pragma unroll
            for (int p = 0; p < NT / 2; p++) {
                uint32_t r0, r1, r2, r3;
                if constexpr (BTRANS) {
                    int n = wn * WTN + p * 16 + (lane & 15);
                    int c = ks * 16 + ((lane >> 4) << 3);
                    ldmx4(r0, r1, r2, r3, bB + (uint32_t)(n * BSTR + c) * 2);
                } else {
                    int kr = ks * 16 + (lane & 7) + ((lane >> 4) << 3);
                    int nc = wn * WTN + p * 16 + (((lane >> 3) & 1) << 3);
                    ldmx4t(r0, r1, r2, r3, bB + (uint32_t)(kr * BSTR + nc) * 2);
                }
                bf[2 * p][0] = r0; bf[2 * p][1] = r2;
                bf[2 * p + 1][0] = r1; bf[2 * p + 1][1] = r3;
            }
            #pragma unroll
            for (int mt = 0; mt < MT; mt++)
                #pragma unroll
                for (int nt = 0; nt < NT; nt++)
                    mma16816(acc[mt][nt], af[mt][0], af[mt][1], af[mt][2], af[mt][3],
                             bf[nt][0], bf[nt][1]);
        }
    };

    const int NKI = K / BKF;
    loadG(0); storeS(0); __syncthreads();
    for (int t = 0; t < NKI; t++) {
        if (t + 1 < NKI) loadG((t + 1) * BKF);
        compute(t & 1);
        if (t + 1 < NKI) { storeS((t + 1) & 1); __syncthreads(); }
    }

    // epilogue
    #pragma unroll
    for (int mt = 0; mt < MT; mt++) {
        int r = row0 + wm * 32 + mt * 16 + (lane >> 2);
        #pragma unroll
        for (int nt = 0; nt < NT; nt++) {
            int cc = col0 + wn * WTN + nt * 8 + ((lane & 3) << 1);
            float b0 = 0.0f, b1 = 0.0f;
            if constexpr (HASBIAS) { b0 = bias[cc]; b1 = bias[cc + 1]; }
            float2 v;
            v.x = acc[mt][nt][0] * scale + b0;
            v.y = acc[mt][nt][1] * scale + b1;
            *reinterpret_cast<float2*>(C + (long long)r * ldc + cc) = v;
            v.x = acc[mt][nt][2] * scale + b0;
            v.y = acc[mt][nt][3] * scale + b1;
            *reinterpret_cast<float2*>(C + (long long)(r + 8) * ldc + cc) = v;
        }
    }
}

// ---------------------------------------------------------------------------
// Row softmax in place: one block per row of 1024 floats, 256 threads.
// ---------------------------------------------------------------------------
__global__ __launch_bounds__(256)
void softmax_kernel(float* __restrict__ P)
{
    float* row = P + (long long)blockIdx.x * 1024;
    const int tid = threadIdx.x;

    float v[4];
    float mx = -1e30f;
    #pragma unroll
    for (int i = 0; i < 4; i++) {
        v[i] = row[tid + 256 * i];
        mx = fmaxf(mx, v[i]);
    }

    __shared__ float red[256];
    red[tid] = mx;
    __syncthreads();
    #pragma unroll
    for (int s = 128; s > 0; s >>= 1) {
        if (tid < s) red[tid] = fmaxf(red[tid], red[tid + s]);
        __syncthreads();
    }
    mx = red[0];
    __syncthreads();

    float sum = 0.0f;
    #pragma unroll
    for (int i = 0; i < 4; i++) {
        v[i] = __expf(v[i] - mx);
        sum += v[i];
    }
    red[tid] = sum;
    __syncthreads();
    #pragma unroll
    for (int s = 128; s > 0; s >>= 1) {
        if (tid < s) red[tid] += red[tid + s];
        __syncthreads();
    }
    const float inv = 1.0f / red[0];

    #pragma unroll
    for (int i = 0; i < 4; i++)
        row[tid + 256 * i] = v[i] * inv;
}

// ---------------------------------------------------------------------------
// Launch
// ---------------------------------------------------------------------------
extern "C" void kernel_launch(void* const* d_in, const int* in_sizes, int n_in,
                              void* d_out, int out_size)
{
    const float* xq  = (const float*)d_in[0];
    const float* xkv = (const float*)d_in[1];
    const float* Wq  = (const float*)d_in[2];
    const float* bq  = (const float*)d_in[3];
    const float* Wk  = (const float*)d_in[4];
    const float* bk  = (const float*)d_in[5];
    const float* Wv  = (const float*)d_in[6];
    const float* bv  = (const float*)d_in[7];
    const float* Wo  = (const float*)d_in[8];
    const float* bo  = (const float*)d_in[9];

    float* out   = (float*)d_out;
    float* probs = out + (long long)ROWS * CH;

    float *Qp, *Kp, *Vp, *Cp;
    cudaGetSymbolAddress((void**)&Qp, g_Q);
    cudaGetSymbolAddress((void**)&Kp, g_K);
    cudaGetSymbolAddress((void**)&Vp, g_V);
    cudaGetSymbolAddress((void**)&Cp, g_C);

    constexpr int SM1 = (2 * 128 * 56 + 2 * 128 * 56) * 2;          // 57344
    constexpr int SM2 = (2 * 128 * 56) * 2 + (2 * 48 * 136) * 2;    // 54784

    cudaFuncSetAttribute((const void*)mma_gemm<128, 128, true, true>,
                         cudaFuncAttributeMaxDynamicSharedMemorySize, SM1);
    cudaFuncSetAttribute((const void*)mma_gemm<128, 128, true, false>,
                         cudaFuncAttributeMaxDynamicSharedMemorySize, SM1);
    cudaFuncSetAttribute((const void*)mma_gemm<128, 64, false, false>,
                         cudaFuncAttributeMaxDynamicSharedMemorySize, SM2);

    // 1-3. Projections: [4096,1024] = X @ W^T + b
    dim3 projGrid(CH / 128, ROWS / 128, 1);
    mma_gemm<128, 128, true, true><<<projGrid, 256, SM1>>>(
        xq,  Wq, Qp, bq, CH, CH, CH, CH, 1, 0, 0, 0, 0, 0, 0, 1.0f);
    mma_gemm<128, 128, true, true><<<projGrid, 256, SM1>>>(
        xkv, Wk, Kp, bk, CH, CH, CH, CH, 1, 0, 0, 0, 0, 0, 0, 1.0f);
    mma_gemm<128, 128, true, true><<<projGrid, 256, SM1>>>(
        xkv, Wv, Vp, bv, CH, CH, CH, CH, 1, 0, 0, 0, 0, 0, 0, 1.0f);

    // 4. Scores: per (bg,h): S[n,m] = (1/8) * q[n,:] . k[m,:], K=64
    dim3 scoreGrid(SEQ / 128, SEQ / 128, BG * HEADS);
    mma_gemm<128, 128, true, false><<<scoreGrid, 256, SM1>>>(
        Qp, Kp, probs, nullptr, HDIM, CH, CH, SEQ,
        HEADS, BG_STRIDE, HDIM, BG_STRIDE, HDIM,
        (long long)HEADS * PROB_BATCH, PROB_BATCH, 0.125f);

    // 5. Softmax rows
    softmax_kernel<<<BG * HEADS * SEQ, 256>>>(probs);

    // 6. PV: Ctx[n,d] = sum_m P[n,m] * V[m, h*64+d]   (B = V, not transposed)
    dim3 pvGrid(1, SEQ / 128, BG * HEADS);
    mma_gemm<128, 64, false, false><<<pvGrid, 256, SM2>>>(
        probs, Vp, Cp, nullptr, SEQ, SEQ, CH, CH,
        HEADS, (long long)HEADS * PROB_BATCH, PROB_BATCH,
        BG_STRIDE, HDIM, BG_STRIDE, HDIM, 1.0f);

    // 7. Output projection
    mma_gemm<128, 128, true, true><<<projGrid, 256, SM1>>>(
        Cp, Wo, out, bo, CH, CH, CH, CH, 1, 0, 0, 0, 0, 0, 0, 1.0f);
}

// round 6
// speedup vs baseline: 1.8471x; 1.0233x over previous
#include <cuda_runtime.h>
#include <cuda_bf16.h>
#include <cstdint>

typedef __nv_bfloat16 bf16;
typedef unsigned short ushortT;

constexpr int BG=4, SEQ=1024, CH=1024, HEADS=16, HDIM=64, ROWS=BG*SEQ;
constexpr long long BG_STRIDE=(long long)SEQ*CH;
constexpr long long PROB_BATCH=(long long)SEQ*SEQ;

// ---- persistent bf16 hi/lo scratch (allocation-free rule) ----
__device__ bf16 g_Xqh[ROWS*CH], g_Xql[ROWS*CH];
__device__ bf16 g_Xkh[ROWS*CH], g_Xkl[ROWS*CH];
__device__ bf16 g_Wqh[CH*CH],  g_Wql[CH*CH];
__device__ bf16 g_Wkh[CH*CH],  g_Wkl[CH*CH];
__device__ bf16 g_Wvh[CH*CH],  g_Wvl[CH*CH];
__device__ bf16 g_Woh[CH*CH],  g_Wol[CH*CH];
__device__ bf16 g_Qh[ROWS*CH], g_Ql[ROWS*CH];
__device__ bf16 g_Kh[ROWS*CH], g_Kl[ROWS*CH];
__device__ bf16 g_Vh[ROWS*CH], g_Vl[ROWS*CH];
__device__ bf16 g_Ch[ROWS*CH], g_Cl[ROWS*CH];
__device__ float g_rowsum[BG*HEADS*SEQ];

// ---------------------------------------------------------------------------
// helpers
// ---------------------------------------------------------------------------
__device__ __forceinline__ uint32_t pack2(ushortT lo, ushortT hi) {
    return (uint32_t)lo | ((uint32_t)hi << 16);
}
__device__ __forceinline__ void bsplit(float x, ushortT& h, ushortT& l) {
    __nv_bfloat16 hb = __float2bfloat16_rn(x);
    h = __bfloat16_as_ushort(hb);
    l = __bfloat16_as_ushort(__float2bfloat16_rn(x - __bfloat162float(hb)));
}
__device__ __forceinline__ void ldmx4(uint32_t& r0, uint32_t& r1, uint32_t& r2, uint32_t& r3, uint32_t a) {
    asm volatile("ldmatrix.sync.aligned.m8n8.x4.shared.b16 {%0,%1,%2,%3},[%4];"
                 : "=r"(r0), "=r"(r1), "=r"(r2), "=r"(r3) : "r"(a));
}
__device__ __forceinline__ void ldmx4t(uint32_t& r0, uint32_t& r1, uint32_t& r2, uint32_t& r3, uint32_t a) {
    asm volatile("ldmatrix.sync.aligned.m8n8.x4.trans.shared.b16 {%0,%1,%2,%3},[%4];"
                 : "=r"(r0), "=r"(r1), "=r"(r2), "=r"(r3) : "r"(a));
}
__device__ __forceinline__ void mma16816(float* c, uint32_t a0, uint32_t a1, uint32_t a2, uint32_t a3,
                                         uint32_t b0, uint32_t b1) {
    asm volatile(
        "mma.sync.aligned.m16n8k16.row.col.f32.bf16.bf16.f32 "
        "{%0,%1,%2,%3},{%4,%5,%6,%7},{%8,%9},{%0,%1,%2,%3};"
        : "+f"(c[0]), "+f"(c[1]), "+f"(c[2]), "+f"(c[3])
        : "r"(a0), "r"(a1), "r"(a2), "r"(a3), "r"(b0), "r"(b1));
}
__device__ __forceinline__ void cpa16(uint32_t dst, const void* src) {
    asm volatile("cp.async.cg.shared.global [%0],[%1],16;" :: "r"(dst), "l"(src));
}
#define CP_COMMIT() asm volatile("cp.async.commit_group;")
#define CP_WAIT1()  asm volatile("cp.async.wait_group 1;")
#define CP_WAIT0()  asm volatile("cp.async.wait_group 0;")

constexpr int ASTR = 24;   // 48B rows: conflict-free ldmatrix for 16-wide bf16 tiles
constexpr int VSTR = 72;   // 144B rows: conflict-free ldmatrix.trans for 64-wide V tiles

// ---------------------------------------------------------------------------
// elementwise fp32 -> bf16 hi/lo split
// ---------------------------------------------------------------------------
__global__ __launch_bounds__(256)
void split_kernel(const float* __restrict__ s, bf16* __restrict__ h, bf16* __restrict__ l)
{
    int i = (blockIdx.x * 256 + threadIdx.x) * 4;
    float4 v = *reinterpret_cast<const float4*>(s + i);
    ushortT hh[4], ll[4];
    bsplit(v.x, hh[0], ll[0]); bsplit(v.y, hh[1], ll[1]);
    bsplit(v.z, hh[2], ll[2]); bsplit(v.w, hh[3], ll[3]);
    *reinterpret_cast<uint2*>(h + i) = make_uint2(pack2(hh[0], hh[1]), pack2(hh[2], hh[3]));
    *reinterpret_cast<uint2*>(l + i) = make_uint2(pack2(ll[0], ll[1]), pack2(ll[2], ll[3]));
}

__global__ void zero_kernel(float* __restrict__ p)
{
    p[blockIdx.x * blockDim.x + threadIdx.x] = 0.0f;
}

// ---------------------------------------------------------------------------
// bf16 NT GEMM with hi/lo compensation (3 mma sweeps per stage).
// C[m,n] = scale * sum_k A[m,k]*B[n,k]   (both K-contiguous)
// EPI: 0 = bias + fp32 out; 1 = bias + bf16 hi/lo out; 2 = exp + fp32 + rowsum
// 256 threads, 8 warps (4x2), BM=BN=128, warp tile 32x64, BK=16.
// ---------------------------------------------------------------------------
template<int EPI>
__global__ __launch_bounds__(256)
void gemm_nt(const bf16* __restrict__ Ah, const bf16* __restrict__ Al,
             const bf16* __restrict__ Bh, const bf16* __restrict__ Bl,
             float* __restrict__ Cf, bf16* __restrict__ Coh, bf16* __restrict__ Col,
             const float* __restrict__ bias, float* __restrict__ rowsum,
             int K, int lda, int ldb, int ldc, int HB,
             long long as1, long long as2, long long bs1, long long bs2,
             long long cs1, long long cs2, float scale)
{
    constexpr int BM = 128, BN = 128;
    constexpr int A_SZ = BM * ASTR, B_SZ = BN * ASTR;
    constexpr int STG = 2 * A_SZ + 2 * B_SZ;    // elems per stage

    extern __shared__ bf16 sm[];
    const int tid = threadIdx.x, lane = tid & 31, warp = tid >> 5;
    const int wm = warp >> 1, wn = warp & 1;
    const int z = blockIdx.z, zo = z / HB, zi = z % HB;
    const long long aoff = zo * as1 + zi * as2;
    const long long boff = zo * bs1 + zi * bs2;
    const long long coff = zo * cs1 + zi * cs2;
    Ah += aoff; Al += aoff; Bh += boff; Bl += boff;
    if (Cf)  Cf  += coff;
    if (Coh) { Coh += coff; Col += coff; }
    const int row0 = blockIdx.y * BM, col0 = blockIdx.x * BN;
    const uint32_t sbase = (uint32_t)__cvta_generic_to_shared(sm);
    const int lr = tid >> 1, lc = (tid & 1) * 8;

    auto loadS = [&](int k0, int buf) {
        uint32_t d = sbase + (uint32_t)(buf * STG) * 2;
        cpa16(d + (uint32_t)(lr * ASTR + lc) * 2,
              Ah + (long long)(row0 + lr) * lda + k0 + lc);
        cpa16(d + (uint32_t)(A_SZ + lr * ASTR + lc) * 2,
              Al + (long long)(row0 + lr) * lda + k0 + lc);
        cpa16(d + (uint32_t)(2 * A_SZ + lr * ASTR + lc) * 2,
              Bh + (long long)(col0 + lr) * ldb + k0 + lc);
        cpa16(d + (uint32_t)(2 * A_SZ + B_SZ + lr * ASTR + lc) * 2,
              Bl + (long long)(col0 + lr) * ldb + k0 + lc);
        CP_COMMIT();
    };

    float acc[2][8][4];
    #pragma unroll
    for (int mt = 0; mt < 2; mt++)
        #pragma unroll
        for (int nt = 0; nt < 8; nt++)
            #pragma unroll
            for (int i = 0; i < 4; i++)
                acc[mt][nt][i] = 0.0f;

    auto compute = [&](int buf) {
        uint32_t s0 = sbase + (uint32_t)(buf * STG) * 2;
        uint32_t ah[2][4], al[2][4];
        #pragma unroll
        for (int mt = 0; mt < 2; mt++) {
            int r = wm * 32 + mt * 16 + (lane & 15), c = (lane >> 4) << 3;
            ldmx4(ah[mt][0], ah[mt][1], ah[mt][2], ah[mt][3],
                  s0 + (uint32_t)(r * ASTR + c) * 2);
            ldmx4(al[mt][0], al[mt][1], al[mt][2], al[mt][3],
                  s0 + (uint32_t)(A_SZ + r * ASTR + c) * 2);
        }
        uint32_t b[8][2];
        #pragma unroll
        for (int p = 0; p < 4; p++) {
            int n = wn * 64 + p * 16 + (lane & 15), c = (lane >> 4) << 3;
            uint32_t r0, r1, r2, r3;
            ldmx4(r0, r1, r2, r3, s0 + (uint32_t)(2 * A_SZ + n * ASTR + c) * 2);
            b[2 * p][0] = r0; b[2 * p][1] = r2; b[2 * p + 1][0] = r1; b[2 * p + 1][1] = r3;
        }
        #pragma unroll
        for (int mt = 0; mt < 2; mt++)
            #pragma unroll
            for (int nt = 0; nt < 8; nt++)
                mma16816(acc[mt][nt], ah[mt][0], ah[mt][1], ah[mt][2], ah[mt][3], b[nt][0], b[nt][1]);
        #pragma unroll
        for (int mt = 0; mt < 2; mt++)
            #pragma unroll
            for (int nt = 0; nt < 8; nt++)
                mma16816(acc[mt][nt], al[mt][0], al[mt][1], al[mt][2], al[mt][3], b[nt][0], b[nt][1]);
        #pragma unroll
        for (int p = 0; p < 4; p++) {
            int n = wn * 64 + p * 16 + (lane & 15), c = (lane >> 4) << 3;
            uint32_t r0, r1, r2, r3;
            ldmx4(r0, r1, r2, r3, s0 + (uint32_t)(2 * A_SZ + B_SZ + n * ASTR + c) * 2);
            b[2 * p][0] = r0; b[2 * p][1] = r2; b[2 * p + 1][0] = r1; b[2 * p + 1][1] = r3;
        }
        #pragma unroll
        for (int mt = 0; mt < 2; mt++)
            #pragma unroll
            for (int nt = 0; nt < 8; nt++)
                mma16816(acc[mt][nt], ah[mt][0], ah[mt][1], ah[mt][2], ah[mt][3], b[nt][0], b[nt][1]);
    };

    const int NKI = K / 16;
    loadS(0, 0);
    for (int t = 0; t < NKI; t++) {
        if (t + 1 < NKI) { loadS((t + 1) * 16, (t + 1) & 1); CP_WAIT1(); }
        else             { CP_WAIT0(); }
        __syncthreads();
        compute(t & 1);
        __syncthreads();
    }

    // epilogue
    #pragma unroll
    for (int mt = 0; mt < 2; mt++) {
        int r = row0 + wm * 32 + mt * 16 + (lane >> 2);
        float rsA = 0.0f, rsB = 0.0f;
        #pragma unroll
        for (int nt = 0; nt < 8; nt++) {
            int c = col0 + wn * 64 + nt * 8 + ((lane & 3) << 1);
            float v0 = acc[mt][nt][0] * scale, v1 = acc[mt][nt][1] * scale;
            float v2 = acc[mt][nt][2] * scale, v3 = acc[mt][nt][3] * scale;
            if constexpr (EPI == 2) {
                v0 = __expf(v0); v1 = __expf(v1); v2 = __expf(v2); v3 = __expf(v3);
                rsA += v0 + v1; rsB += v2 + v3;
                *reinterpret_cast<float2*>(Cf + (long long)r * ldc + c)       = make_float2(v0, v1);
                *reinterpret_cast<float2*>(Cf + (long long)(r + 8) * ldc + c) = make_float2(v2, v3);
            } else if constexpr (EPI == 0) {
                float b0 = bias[c], b1 = bias[c + 1];
                *reinterpret_cast<float2*>(Cf + (long long)r * ldc + c)       = make_float2(v0 + b0, v1 + b1);
                *reinterpret_cast<float2*>(Cf + (long long)(r + 8) * ldc + c) = make_float2(v2 + b0, v3 + b1);
            } else {
                float b0 = bias[c], b1 = bias[c + 1];
                float x0 = v0 + b0, x1 = v1 + b1, x2 = v2 + b0, x3 = v3 + b1;
                ushortT h0, l0, h1, l1, h2, l2, h3, l3;
                bsplit(x0, h0, l0); bsplit(x1, h1, l1); bsplit(x2, h2, l2); bsplit(x3, h3, l3);
                *reinterpret_cast<uint32_t*>(Coh + (long long)r * ldc + c)       = pack2(h0, h1);
                *reinterpret_cast<uint32_t*>(Col + (long long)r * ldc + c)       = pack2(l0, l1);
                *reinterpret_cast<uint32_t*>(Coh + (long long)(r + 8) * ldc + c) = pack2(h2, h3);
                *reinterpret_cast<uint32_t*>(Col + (long long)(r + 8) * ldc + c) = pack2(l2, l3);
            }
        }
        if constexpr (EPI == 2) {
            rsA += __shfl_xor_sync(0xFFFFFFFFu, rsA, 1);
            rsA += __shfl_xor_sync(0xFFFFFFFFu, rsA, 2);
            rsB += __shfl_xor_sync(0xFFFFFFFFu, rsB, 1);
            rsB += __shfl_xor_sync(0xFFFFFFFFu, rsB, 2);
            if ((lane & 3) == 0) {
                atomicAdd(&rowsum[(long long)z * SEQ + r], rsA);
                atomicAdd(&rowsum[(long long)z * SEQ + r + 8], rsB);
            }
        }
    }
}

// ---------------------------------------------------------------------------
// PV kernel: reads E (unnormalized exp scores), normalizes by 1/rowsum,
// writes probs in place, and computes context (bf16 hi/lo out).
// BM=128, BN=64, K=SEQ. grid (1, 8, 64).
// ---------------------------------------------------------------------------
__global__ __launch_bounds__(256)
void pv_kernel(float* __restrict__ P,
               const bf16* __restrict__ Vh, const bf16* __restrict__ Vl,
               const float* __restrict__ rowsum,
               bf16* __restrict__ Coh, bf16* __restrict__ Col)
{
    constexpr int BM = 128;
    constexpr int A_SZ = BM * ASTR;
    constexpr int V_SZ = 16 * VSTR;
    constexpr int STG = 2 * A_SZ + 2 * V_SZ;

    extern __shared__ bf16 sm[];
    const int tid = threadIdx.x, lane = tid & 31, warp = tid >> 5;
    const int wm = warp >> 1, wn = warp & 1;
    const int z = blockIdx.z, zo = z >> 4, zi = z & 15;
    const int row0 = blockIdx.y * BM;
    float* Pz = P + (long long)z * PROB_BATCH;
    const bf16* Vhz = Vh + zo * BG_STRIDE + zi * HDIM;
    const bf16* Vlz = Vl + zo * BG_STRIDE + zi * HDIM;
    const uint32_t sbase = (uint32_t)__cvta_generic_to_shared(sm);

    const int ar = tid >> 1, ac = (tid & 1) * 8;
    const float inv = 1.0f / rowsum[(long long)z * SEQ + row0 + ar];

    float4 e0, e1;
    auto loadE = [&](int m0) {
        const float* p = Pz + (long long)(row0 + ar) * SEQ + m0 + ac;
        e0 = *reinterpret_cast<const float4*>(p);
        e1 = *reinterpret_cast<const float4*>(p + 4);
    };
    auto cpaV = [&](int m0, int buf) {
        if (tid < 128) {
            int vr = tid >> 3, vc = (tid & 7) * 8;
            uint32_t d = sbase + (uint32_t)(buf * STG + 2 * A_SZ + vr * VSTR + vc) * 2;
            cpa16(d, Vhz + (long long)(m0 + vr) * CH + vc);
            cpa16(d + (uint32_t)V_SZ * 2, Vlz + (long long)(m0 + vr) * CH + vc);
        }
        CP_COMMIT();
    };
    auto storeA = [&](int m0, int buf) {
        float w[8] = { e0.x * inv, e0.y * inv, e0.z * inv, e0.w * inv,
                       e1.x * inv, e1.y * inv, e1.z * inv, e1.w * inv };
        float* p = Pz + (long long)(row0 + ar) * SEQ + m0 + ac;
        *reinterpret_cast<float4*>(p)     = make_float4(w[0], w[1], w[2], w[3]);
        *reinterpret_cast<float4*>(p + 4) = make_float4(w[4], w[5], w[6], w[7]);
        ushortT hh[8], ll[8];
        #pragma unroll
        for (int j = 0; j < 8; j++) bsplit(w[j], hh[j], ll[j]);
        bf16* dh = sm + buf * STG + ar * ASTR + ac;
        *reinterpret_cast<uint4*>(dh) = make_uint4(
            pack2(hh[0], hh[1]), pack2(hh[2], hh[3]), pack2(hh[4], hh[5]), pack2(hh[6], hh[7]));
        *reinterpret_cast<uint4*>(dh + A_SZ) = make_uint4(
            pack2(ll[0], ll[1]), pack2(ll[2], ll[3]), pack2(ll[4], ll[5]), pack2(ll[6], ll[7]));
    };

    float acc[2][4][4];
    #pragma unroll
    for (int mt = 0; mt < 2; mt++)
        #pragma unroll
        for (int nt = 0; nt < 4; nt++)
            #pragma unroll
            for (int i = 0; i < 4; i++)
                acc[mt][nt][i] = 0.0f;

    auto compute = [&](int buf) {
        uint32_t s0 = sbase + (uint32_t)(buf * STG) * 2;
        uint32_t wh[2][4], wl[2][4];
        #pragma unroll
        for (int mt = 0; mt < 2; mt++) {
            int r = wm * 32 + mt * 16 + (lane & 15), c = (lane >> 4) << 3;
            ldmx4(wh[mt][0], wh[mt][1], wh[mt][2], wh[mt][3], s0 + (uint32_t)(r * ASTR + c) * 2);
            ldmx4(wl[mt][0], wl[mt][1], wl[mt][2], wl[mt][3], s0 + (uint32_t)(A_SZ + r * ASTR + c) * 2);
        }
        uint32_t bv[4][2];
        #pragma unroll
        for (int p = 0; p < 2; p++) {
            int kr = (lane & 7) + ((lane >> 4) << 3);
            int nc = wn * 32 + p * 16 + (((lane >> 3) & 1) << 3);
            uint32_t r0, r1, r2, r3;
            ldmx4t(r0, r1, r2, r3, s0 + (uint32_t)(2 * A_SZ + kr * VSTR + nc) * 2);
            bv[2 * p][0] = r0; bv[2 * p][1] = r2; bv[2 * p + 1][0] = r1; bv[2 * p + 1][1] = r3;
        }
        #pragma unroll
        for (int mt = 0; mt < 2; mt++)
            #pragma unroll
            for (int nt = 0; nt < 4; nt++)
                mma16816(acc[mt][nt], wh[mt][0], wh[mt][1], wh[mt][2], wh[mt][3], bv[nt][0], bv[nt][1]);
        #pragma unroll
        for (int mt = 0; mt < 2; mt++)
            #pragma unroll
            for (int nt = 0; nt < 4; nt++)
                mma16816(acc[mt][nt], wl[mt][0], wl[mt][1], wl[mt][2], wl[mt][3], bv[nt][0], bv[nt][1]);
        #pragma unroll
        for (int p = 0; p < 2; p++) {
            int kr = (lane & 7) + ((lane >> 4) << 3);
            int nc = wn * 32 + p * 16 + (((lane >> 3) & 1) << 3);
            uint32_t r0, r1, r2, r3;
            ldmx4t(r0, r1, r2, r3, s0 + (uint32_t)(2 * A_SZ + V_SZ + kr * VSTR + nc) * 2);
            bv[2 * p][0] = r0; bv[2 * p][1] = r2; bv[2 * p + 1][0] = r1; bv[2 * p + 1][1] = r3;
        }
        #pragma unroll
        for (int mt = 0; mt < 2; mt++)
            #pragma unroll
            for (int nt = 0; nt < 4; nt++)
                mma16816(acc[mt][nt], wh[mt][0], wh[mt][1], wh[mt][2], wh[mt][3], bv[nt][0], bv[nt][1]);
    };

    loadE(0);
    cpaV(0, 0);
    storeA(0, 0);
    constexpr int NKI = SEQ / 16;
    for (int t = 0; t < NKI; t++) {
        int nb = (t + 1) & 1;
        if (t + 1 < NKI) { loadE((t + 1) * 16); cpaV((t + 1) * 16, nb); CP_WAIT1(); }
        else             { CP_WAIT0(); }
        __syncthreads();
        compute(t & 1);
        if (t + 1 < NKI) storeA((t + 1) * 16, nb);
        __syncthreads();
    }

    // epilogue: split context to bf16 hi/lo
    bf16* Chz = Coh + zo * BG_STRIDE + zi * HDIM;
    bf16* Clz = Col + zo * BG_STRIDE + zi * HDIM;
    #pragma unroll
    for (int mt = 0; mt < 2; mt++) {
        int r = row0 + wm * 32 + mt * 16 + (lane >> 2);
        #pragma unroll
        for (int nt = 0; nt < 4; nt++) {
            int c = wn * 32 + nt * 8 + ((lane & 3) << 1);
            ushortT h0, l0, h1, l1, h2, l2, h3, l3;
            bsplit(acc[mt][nt][0], h0, l0); bsplit(acc[mt][nt][1], h1, l1);
            bsplit(acc[mt][nt][2], h2, l2); bsplit(acc[mt][nt][3], h3, l3);
            *reinterpret_cast<uint32_t*>(Chz + (long long)r * CH + c)       = pack2(h0, h1);
            *reinterpret_cast<uint32_t*>(Clz + (long long)r * CH + c)       = pack2(l0, l1);
            *reinterpret_cast<uint32_t*>(Chz + (long long)(r + 8) * CH + c) = pack2(h2, h3);
            *reinterpret_cast<uint32_t*>(Clz + (long long)(r + 8) * CH + c) = pack2(l2, l3);
        }
    }
}

// ---------------------------------------------------------------------------
// Launch
// ---------------------------------------------------------------------------
extern "C" void kernel_launch(void* const* d_in, const int* in_sizes, int n_in,
                              void* d_out, int out_size)
{
    const float* xq  = (const float*)d_in[0];
    const float* xkv = (const float*)d_in[1];
    const float* Wq  = (const float*)d_in[2];
    const float* bq  = (const float*)d_in[3];
    const float* Wk  = (const float*)d_in[4];
    const float* bk  = (const float*)d_in[5];
    const float* Wv  = (const float*)d_in[6];
    const float* bv  = (const float*)d_in[7];
    const float* Wo  = (const float*)d_in[8];
    const float* bo  = (const float*)d_in[9];

    float* out   = (float*)d_out;
    float* probs = out + (long long)ROWS * CH;

    bf16 *Xqh, *Xql, *Xkh, *Xkl, *Wqh, *Wql, *Wkh, *Wkl, *Wvh, *Wvl, *Woh, *Wol;
    bf16 *Qh, *Ql, *Kh, *Kl, *Vh, *Vl, *Ch, *Cl;
    float* rsum;
    cudaGetSymbolAddress((void**)&Xqh, g_Xqh); cudaGetSymbolAddress((void**)&Xql, g_Xql);
    cudaGetSymbolAddress((void**)&Xkh, g_Xkh); cudaGetSymbolAddress((void**)&Xkl, g_Xkl);
    cudaGetSymbolAddress((void**)&Wqh, g_Wqh); cudaGetSymbolAddress((void**)&Wql, g_Wql);
    cudaGetSymbolAddress((void**)&Wkh, g_Wkh); cudaGetSymbolAddress((void**)&Wkl, g_Wkl);
    cudaGetSymbolAddress((void**)&Wvh, g_Wvh); cudaGetSymbolAddress((void**)&Wvl, g_Wvl);
    cudaGetSymbolAddress((void**)&Woh, g_Woh); cudaGetSymbolAddress((void**)&Wol, g_Wol);
    cudaGetSymbolAddress((void**)&Qh, g_Qh);   cudaGetSymbolAddress((void**)&Ql, g_Ql);
    cudaGetSymbolAddress((void**)&Kh, g_Kh);   cudaGetSymbolAddress((void**)&Kl, g_Kl);
    cudaGetSymbolAddress((void**)&Vh, g_Vh);   cudaGetSymbolAddress((void**)&Vl, g_Vl);
    cudaGetSymbolAddress((void**)&Ch, g_Ch);   cudaGetSymbolAddress((void**)&Cl, g_Cl);
    cudaGetSymbolAddress((void**)&rsum, g_rowsum);

    constexpr int SM_G  = (2 * (2 * 128 * ASTR + 2 * 128 * ASTR)) * 2;          // 49152
    constexpr int SM_PV = (2 * (2 * 128 * ASTR + 2 * 16 * VSTR)) * 2;           // 33792
    cudaFuncSetAttribute((const void*)gemm_nt<0>, cudaFuncAttributeMaxDynamicSharedMemorySize, SM_G);
    cudaFuncSetAttribute((const void*)gemm_nt<1>, cudaFuncAttributeMaxDynamicSharedMemorySize, SM_G);
    cudaFuncSetAttribute((const void*)gemm_nt<2>, cudaFuncAttributeMaxDynamicSharedMemorySize, SM_G);
    cudaFuncSetAttribute((const void*)pv_kernel,  cudaFuncAttributeMaxDynamicSharedMemorySize, SM_PV);

    // 0. zero rowsums + split inputs/weights to bf16 hi/lo
    zero_kernel<<<BG * HEADS, SEQ>>>(rsum);
    split_kernel<<<ROWS * CH / 1024, 256>>>(xq,  Xqh, Xql);
    split_kernel<<<ROWS * CH / 1024, 256>>>(xkv, Xkh, Xkl);
    split_kernel<<<CH * CH / 1024, 256>>>(Wq, Wqh, Wql);
    split_kernel<<<CH * CH / 1024, 256>>>(Wk, Wkh, Wkl);
    split_kernel<<<CH * CH / 1024, 256>>>(Wv, Wvh, Wvl);
    split_kernel<<<CH * CH / 1024, 256>>>(Wo, Woh, Wol);

    // 1-3. projections -> bf16 hi/lo Q,K,V
    dim3 projGrid(CH / 128, ROWS / 128, 1);
    gemm_nt<1><<<projGrid, 256, SM_G>>>(Xqh, Xql, Wqh, Wql, nullptr, Qh, Ql, bq, nullptr,
                                        CH, CH, CH, CH, 1, 0, 0, 0, 0, 0, 0, 1.0f);
    gemm_nt<1><<<projGrid, 256, SM_G>>>(Xkh, Xkl, Wkh, Wkl, nullptr, Kh, Kl, bk, nullptr,
                                        CH, CH, CH, CH, 1, 0, 0, 0, 0, 0, 0, 1.0f);
    gemm_nt<1><<<projGrid, 256, SM_G>>>(Xkh, Xkl, Wvh, Wvl, nullptr, Vh, Vl, bv, nullptr,
                                        CH, CH, CH, CH, 1, 0, 0, 0, 0, 0, 0, 1.0f);

    // 4. scores -> E = exp(s/8) + row sums (no separate softmax pass)
    dim3 scoreGrid(SEQ / 128, SEQ / 128, BG * HEADS);
    gemm_nt<2><<<scoreGrid, 256, SM_G>>>(Qh, Ql, Kh, Kl, probs, nullptr, nullptr, nullptr, rsum,
                                         HDIM, CH, CH, SEQ,
                                         HEADS, BG_STRIDE, HDIM, BG_STRIDE, HDIM,
                                         (long long)HEADS * PROB_BATCH, PROB_BATCH, 0.125f);

    // 5. PV: normalize probs in place + context (bf16 hi/lo)
    dim3 pvGrid(1, SEQ / 128, BG * HEADS);
    pv_kernel<<<pvGrid, 256, SM_PV>>>(probs, Vh, Vl, rsum, Ch, Cl);

    // 6. output projection (fp32 out)
    gemm_nt<0><<<projGrid, 256, SM_G>>>(Ch, Cl, Woh, Wol, out, nullptr, nullptr, bo, nullptr,
                                        CH, CH, CH, CH, 1, 0, 0, 0, 0, 0, 0, 1.0f);
}

// round 10
// speedup vs baseline: 1.9840x; 1.0741x over previous
#include <cuda_runtime.h>
#include <cuda_bf16.h>
#include <cstdint>

typedef __nv_bfloat16 bf16;
typedef unsigned short ushortT;

constexpr int BG=4, SEQ=1024, CH=1024, HEADS=16, HDIM=64;
constexpr int ROWS = BG * SEQ;
constexpr long long BG_STRIDE  = (long long)SEQ * CH;
constexpr long long PROB_BATCH = (long long)SEQ * SEQ;

// ---- persistent bf16 hi/lo scratch (allocation-free rule) ----
__device__ __align__(256) bf16 g_Xqh[ROWS*CH], g_Xql[ROWS*CH];
__device__ __align__(256) bf16 g_Xkh[ROWS*CH], g_Xkl[ROWS*CH];
__device__ __align__(256) bf16 g_Wqh[CH*CH],  g_Wql[CH*CH];
__device__ __align__(256) bf16 g_Wkh[CH*CH],  g_Wkl[CH*CH];
__device__ __align__(256) bf16 g_Wvh[CH*CH],  g_Wvl[CH*CH];
__device__ __align__(256) bf16 g_Woh[CH*CH],  g_Wol[CH*CH];
__device__ __align__(256) bf16 g_Qh[ROWS*CH], g_Ql[ROWS*CH];
__device__ __align__(256) bf16 g_Kh[ROWS*CH], g_Kl[ROWS*CH];
__device__ __align__(256) bf16 g_Vh[ROWS*CH], g_Vl[ROWS*CH];
__device__ __align__(256) bf16 g_Ch[ROWS*CH], g_Cl[ROWS*CH];
__device__ float g_rowsum[BG*HEADS*SEQ];

// ---------------------------------------------------------------------------
// helpers
// ---------------------------------------------------------------------------
__device__ __forceinline__ uint32_t pack2(ushortT lo, ushortT hi) {
    return (uint32_t)lo | ((uint32_t)hi << 16);
}
__device__ __forceinline__ void bsplit(float x, ushortT& h, ushortT& l) {
    __nv_bfloat16 hb = __float2bfloat16_rn(x);
    h = __bfloat16_as_ushort(hb);
    l = __bfloat16_as_ushort(__float2bfloat16_rn(x - __bfloat162float(hb)));
}
__device__ __forceinline__ void ldmx4(uint32_t& r0, uint32_t& r1, uint32_t& r2, uint32_t& r3, uint32_t a) {
    asm volatile("ldmatrix.sync.aligned.m8n8.x4.shared.b16 {%0,%1,%2,%3},[%4];"
                 : "=r"(r0), "=r"(r1), "=r"(r2), "=r"(r3) : "r"(a));
}
__device__ __forceinline__ void ldmx4t(uint32_t& r0, uint32_t& r1, uint32_t& r2, uint32_t& r3, uint32_t a) {
    asm volatile("ldmatrix.sync.aligned.m8n8.x4.trans.shared.b16 {%0,%1,%2,%3},[%4];"
                 : "=r"(r0), "=r"(r1), "=r"(r2), "=r"(r3) : "r"(a));
}
__device__ __forceinline__ void mma16816(float* c, uint32_t a0, uint32_t a1, uint32_t a2, uint32_t a3,
                                         uint32_t b0, uint32_t b1) {
    asm volatile(
        "mma.sync.aligned.m16n8k16.row.col.f32.bf16.bf16.f32 "
        "{%0,%1,%2,%3},{%4,%5,%6,%7},{%8,%9},{%0,%1,%2,%3};"
        : "+f"(c[0]), "+f"(c[1]), "+f"(c[2]), "+f"(c[3])
        : "r"(a0), "r"(a1), "r"(a2), "r"(a3), "r"(b0), "r"(b1));
}
__device__ __forceinline__ void cpa16(uint32_t dst, const void* src) {
    asm volatile("cp.async.cg.shared.global [%0],[%1],16;" :: "r"(dst), "l"(src));
}
#define CP_COMMIT() asm volatile("cp.async.commit_group;")
#define CP_WAIT1()  asm volatile("cp.async.wait_group 1;")
#define CP_WAIT0()  asm volatile("cp.async.wait_group 0;")

// ---------------------------------------------------------------------------
// Dense bf16 NT GEMM body (3-sweep hi/lo compensation).
// C[m,n] = scale * sum_k A[m,k]*B[n,k]. BM=BN=128, BK=16 fp32.
// 3-stage cp.async ring; per k-tile: wait -> ONE __syncthreads -> load(t+2)
// -> compute(t).  (wait precedes the barrier: cp.async cross-thread
// visibility; load(t+2) overwrites stage (t-1)%3, which every thread
// finished computing before this barrier.)
// EPI: 0 = bias + fp32 out; 1 = bias + bf16 hi/lo out; 2 = exp + fp32 + rowsum
// ---------------------------------------------------------------------------
constexpr int ASTR = 24;                  // 48B rows, conflict-free ldmatrix
constexpr int A_SZ = 128 * ASTR;          // 3072 elems per matrix
constexpr int D_STG = 4 * A_SZ;           // Ah,Al,Bh,Bl
constexpr int SM_DENSE = 3 * D_STG * 2;   // 73728 B

template<int EPI>
__device__ __forceinline__ void gemm_body(
    const bf16* __restrict__ Ah, const bf16* __restrict__ Al,
    const bf16* __restrict__ Bh, const bf16* __restrict__ Bl,
    float* __restrict__ Cf, bf16* __restrict__ Coh, bf16* __restrict__ Col,
    const float* __restrict__ bias, float* __restrict__ rowsum,
    int K, int lda, int ldb, int ldc, float scale, int row0, int col0)
{
    extern __shared__ bf16 sm[];
    const uint32_t sbase = (uint32_t)__cvta_generic_to_shared(sm);
    const int tid = threadIdx.x, lane = tid & 31, warp = tid >> 5;
    const int wm = warp >> 1, wn = warp & 1;

    auto loadS = [&](int kt, int s) {
        #pragma unroll
        for (int i = 0; i < 4; i++) {
            int e = tid + i * 256;
            int b = e >> 8, q = e & 255, row = q >> 1, ch = (q & 1) * 8;
            const bf16* base = (b == 0) ? Ah : (b == 1) ? Al : (b == 2) ? Bh : Bl;
            int rb = (b < 2) ? row0 : col0;
            int ld = (b < 2) ? lda : ldb;
            cpa16(sbase + (uint32_t)(s * D_STG + b * A_SZ + row * ASTR + ch) * 2,
                  base + (long long)(rb + row) * ld + kt * 16 + ch);
        }
        CP_COMMIT();
    };

    float acc[2][8][4];
    #pragma unroll
    for (int mt = 0; mt < 2; mt++)
        #pragma unroll
        for (int nt = 0; nt < 8; nt++)
            #pragma unroll
            for (int i = 0; i < 4; i++)
                acc[mt][nt][i] = 0.0f;

    auto compute = [&](int s) {
        uint32_t s0 = sbase + (uint32_t)(s * D_STG) * 2;
        uint32_t ah[2][4], al[2][4];
        #pragma unroll
        for (int mt = 0; mt < 2; mt++) {
            int r = wm * 32 + mt * 16 + (lane & 15), c = (lane >> 4) << 3;
            ldmx4(ah[mt][0], ah[mt][1], ah[mt][2], ah[mt][3], s0 + (uint32_t)(r * ASTR + c) * 2);
            ldmx4(al[mt][0], al[mt][1], al[mt][2], al[mt][3], s0 + (uint32_t)(A_SZ + r * ASTR + c) * 2);
        }
        uint32_t b[8][2];
        #pragma unroll
        for (int p = 0; p < 4; p++) {
            int n = wn * 64 + p * 16 + (lane & 15), c = (lane >> 4) << 3;
            uint32_t r0, r1, r2, r3;
            ldmx4(r0, r1, r2, r3, s0 + (uint32_t)(2 * A_SZ + n * ASTR + c) * 2);
            b[2 * p][0] = r0; b[2 * p][1] = r2; b[2 * p + 1][0] = r1; b[2 * p + 1][1] = r3;
        }
        #pragma unroll
        for (int mt = 0; mt < 2; mt++)
            #pragma unroll
            for (int nt = 0; nt < 8; nt++)
                mma16816(acc[mt][nt], ah[mt][0], ah[mt][1], ah[mt][2], ah[mt][3], b[nt][0], b[nt][1]);
        #pragma unroll
        for (int mt = 0; mt < 2; mt++)
            #pragma unroll
            for (int nt = 0; nt < 8; nt++)
                mma16816(acc[mt][nt], al[mt][0], al[mt][1], al[mt][2], al[mt][3], b[nt][0], b[nt][1]);
        #pragma unroll
        for (int p = 0; p < 4; p++) {
            int n = wn * 64 + p * 16 + (lane & 15), c = (lane >> 4) << 3;
            uint32_t r0, r1, r2, r3;
            ldmx4(r0, r1, r2, r3, s0 + (uint32_t)(3 * A_SZ + n * ASTR + c) * 2);
            b[2 * p][0] = r0; b[2 * p][1] = r2; b[2 * p + 1][0] = r1; b[2 * p + 1][1] = r3;
        }
        #pragma unroll
        for (int mt = 0; mt < 2; mt++)
            #pragma unroll
            for (int nt = 0; nt < 8; nt++)
                mma16816(acc[mt][nt], ah[mt][0], ah[mt][1], ah[mt][2], ah[mt][3], b[nt][0], b[nt][1]);
    };

    const int NKI = K / 16;
    loadS(0, 0);
    if (NKI > 1) loadS(1, 1);
    for (int t = 0; t < NKI; t++) {
        if (t + 1 < NKI) CP_WAIT1(); else CP_WAIT0();   // stage t landed (this thread)
        __syncthreads();                                 // visible to all; compute(t-1) done by all
        if (t + 2 < NKI) loadS(t + 2, (t + 2) % 3);      // overwrites stage (t-1)%3 — safe
        compute(t % 3);
    }

    // epilogue
    #pragma unroll
    for (int mt = 0; mt < 2; mt++) {
        int r = row0 + wm * 32 + mt * 16 + (lane >> 2);
        float rsA = 0.0f, rsB = 0.0f;
        #pragma unroll
        for (int nt = 0; nt < 8; nt++) {
            int c = col0 + wn * 64 + nt * 8 + ((lane & 3) << 1);
            float v0 = acc[mt][nt][0] * scale, v1 = acc[mt][nt][1] * scale;
            float v2 = acc[mt][nt][2] * scale, v3 = acc[mt][nt][3] * scale;
            if constexpr (EPI == 2) {
                v0 = __expf(v0); v1 = __expf(v1); v2 = __expf(v2); v3 = __expf(v3);
                rsA += v0 + v1; rsB += v2 + v3;
                *reinterpret_cast<float2*>(Cf + (long long)r * ldc + c)       = make_float2(v0, v1);
                *reinterpret_cast<float2*>(Cf + (long long)(r + 8) * ldc + c) = make_float2(v2, v3);
            } else if constexpr (EPI == 0) {
                float b0 = bias[c], b1 = bias[c + 1];
                *reinterpret_cast<float2*>(Cf + (long long)r * ldc + c)       = make_float2(v0 + b0, v1 + b1);
                *reinterpret_cast<float2*>(Cf + (long long)(r + 8) * ldc + c) = make_float2(v2 + b0, v3 + b1);
            } else {
                float b0 = bias[c], b1 = bias[c + 1];
                float x0 = v0 + b0, x1 = v1 + b1, x2 = v2 + b0, x3 = v3 + b1;
                ushortT h0, l0, h1, l1, h2, l2, h3, l3;
                bsplit(x0, h0, l0); bsplit(x1, h1, l1); bsplit(x2, h2, l2); bsplit(x3, h3, l3);
                *reinterpret_cast<uint32_t*>(Coh + (long long)r * ldc + c)       = pack2(h0, h1);
                *reinterpret_cast<uint32_t*>(Col + (long long)r * ldc + c)       = pack2(l0, l1);
                *reinterpret_cast<uint32_t*>(Coh + (long long)(r + 8) * ldc + c) = pack2(h2, h3);
                *reinterpret_cast<uint32_t*>(Col + (long long)(r + 8) * ldc + c) = pack2(l2, l3);
            }
        }
        if constexpr (EPI == 2) {
            rsA += __shfl_xor_sync(0xFFFFFFFFu, rsA, 1);
            rsA += __shfl_xor_sync(0xFFFFFFFFu, rsA, 2);
            rsB += __shfl_xor_sync(0xFFFFFFFFu, rsB, 1);
            rsB += __shfl_xor_sync(0xFFFFFFFFu, rsB, 2);
            if ((lane & 3) == 0) {
                atomicAdd(&rowsum[r], rsA);
                atomicAdd(&rowsum[r + 8], rsB);
            }
        }
    }
}

// ---------------------------------------------------------------------------
// kernel wrappers
// ---------------------------------------------------------------------------
struct ProjArgs {
    const bf16 *Ah[3], *Al[3], *Bh[3], *Bl[3];
    bf16 *Ch[3], *Cl[3];
    const float* bias[3];
};

__global__ __launch_bounds__(256, 2)
void proj_kernel(ProjArgs p)
{
    const int z = blockIdx.z;
    gemm_body<1>(p.Ah[z], p.Al[z], p.Bh[z], p.Bl[z],
                 nullptr, p.Ch[z], p.Cl[z], p.bias[z], nullptr,
                 CH, CH, CH, CH, 1.0f, blockIdx.y * 128, blockIdx.x * 128);
}

__global__ __launch_bounds__(256, 2)
void out_kernel(const bf16* __restrict__ Ch, const bf16* __restrict__ Cl,
                const bf16* __restrict__ Wh, const bf16* __restrict__ Wl,
                float* __restrict__ out, const float* __restrict__ bo)
{
    gemm_body<0>(Ch, Cl, Wh, Wl, out, nullptr, nullptr, bo, nullptr,
                 CH, CH, CH, CH, 1.0f, blockIdx.y * 128, blockIdx.x * 128);
}

__global__ __launch_bounds__(256, 2)
void score_kernel(const bf16* __restrict__ Qh, const bf16* __restrict__ Ql,
                  const bf16* __restrict__ Kh, const bf16* __restrict__ Kl,
                  float* __restrict__ probs, float* __restrict__ rowsum)
{
    const int z = blockIdx.z, zo = z >> 4, zi = z & 15;
    const long long off = zo * BG_STRIDE + (long long)zi * HDIM;
    gemm_body<2>(Qh + off, Ql + off, Kh + off, Kl + off,
                 probs + (long long)z * PROB_BATCH, nullptr, nullptr, nullptr,
                 rowsum + (long long)z * SEQ,
                 HDIM, CH, CH, SEQ, 0.125f, blockIdx.y * 128, blockIdx.x * 128);
}

// ---------------------------------------------------------------------------
// elementwise fp32 -> bf16 hi/lo split + zero
// ---------------------------------------------------------------------------
__global__ __launch_bounds__(256)
void split_kernel(const float* __restrict__ s, bf16* __restrict__ h, bf16* __restrict__ l)
{
    int i = (blockIdx.x * 256 + threadIdx.x) * 4;
    float4 v = *reinterpret_cast<const float4*>(s + i);
    ushortT hh[4], ll[4];
    bsplit(v.x, hh[0], ll[0]); bsplit(v.y, hh[1], ll[1]);
    bsplit(v.z, hh[2], ll[2]); bsplit(v.w, hh[3], ll[3]);
    *reinterpret_cast<uint2*>(h + i) = make_uint2(pack2(hh[0], hh[1]), pack2(hh[2], hh[3]));
    *reinterpret_cast<uint2*>(l + i) = make_uint2(pack2(ll[0], ll[1]), pack2(ll[2], ll[3]));
}

__global__ void zero_kernel(float* __restrict__ p)
{
    p[blockIdx.x * blockDim.x + threadIdx.x] = 0.0f;
}

// ---------------------------------------------------------------------------
// PV kernel: reads E, normalizes by 1/rowsum, writes probs in place,
// computes context (bf16 hi/lo out). BM=128, BN=64, BK=32 fp32, K=SEQ.
// (2-stage; wait -> barrier -> compute ordering preserved from round 5/6.)
// ---------------------------------------------------------------------------
constexpr int PSTR  = 40;                  // 80B rows, conflict-free for 32-wide tiles
constexpr int VSTR  = 72;                  // 144B rows, conflict-free ldmatrix.trans 64-wide
constexpr int P_SZ  = 128 * PSTR;          // 5120
constexpr int V_SZ  = 32 * VSTR;           // 2304
constexpr int PV_STG = 2 * P_SZ + 2 * V_SZ;
constexpr int SM_PV  = 2 * PV_STG * 2;     // 59392 B

__global__ __launch_bounds__(256, 2)
void pv_kernel(float* __restrict__ P,
               const bf16* __restrict__ Vh, const bf16* __restrict__ Vl,
               const float* __restrict__ rowsum,
               bf16* __restrict__ Coh, bf16* __restrict__ Col)
{
    extern __shared__ bf16 sm[];
    const int tid = threadIdx.x, lane = tid & 31, warp = tid >> 5;
    const int wm = warp >> 1, wn = warp & 1;
    const int z = blockIdx.z, zo = z >> 4, zi = z & 15;
    const int row0 = blockIdx.y * 128;
    float* Pz = P + (long long)z * PROB_BATCH;
    const bf16* Vhz = Vh + zo * BG_STRIDE + (long long)zi * HDIM;
    const bf16* Vlz = Vl + zo * BG_STRIDE + (long long)zi * HDIM;
    const uint32_t sbase = (uint32_t)__cvta_generic_to_shared(sm);

    const int ar = tid >> 1, ac = (tid & 1) * 16;
    const float inv = 1.0f / rowsum[(long long)z * SEQ + row0 + ar];

    float4 e[4];
    auto loadE = [&](int m0) {
        const float* p = Pz + (long long)(row0 + ar) * SEQ + m0 + ac;
        e[0] = *reinterpret_cast<const float4*>(p);
        e[1] = *reinterpret_cast<const float4*>(p + 4);
        e[2] = *reinterpret_cast<const float4*>(p + 8);
        e[3] = *reinterpret_cast<const float4*>(p + 12);
    };
    auto cpaV = [&](int m0, int buf) {
        #pragma unroll
        for (int i = 0; i < 2; i++) {
            int q = (tid + i * 256);
            int b = q >> 8, qq = q & 255;
            int vr = qq >> 3, vc = (qq & 7) * 8;
            const bf16* src = (b ? Vlz : Vhz) + (long long)(m0 + vr) * CH + vc;
            cpa16(sbase + (uint32_t)(buf * PV_STG + 2 * P_SZ + b * V_SZ + vr * VSTR + vc) * 2, src);
        }
        CP_COMMIT();
    };
    auto storeA = [&](int m0, int buf) {
        float w[16];
        #pragma unroll
        for (int j = 0; j < 4; j++) {
            w[4 * j + 0] = e[j].x * inv; w[4 * j + 1] = e[j].y * inv;
            w[4 * j + 2] = e[j].z * inv; w[4 * j + 3] = e[j].w * inv;
        }
        float* p = Pz + (long long)(row0 + ar) * SEQ + m0 + ac;
        #pragma unroll
        for (int j = 0; j < 4; j++)
            *reinterpret_cast<float4*>(p + 4 * j) = make_float4(w[4 * j], w[4 * j + 1], w[4 * j + 2], w[4 * j + 3]);
        ushortT hh[16], ll[16];
        #pragma unroll
        for (int j = 0; j < 16; j++) bsplit(w[j], hh[j], ll[j]);
        bf16* dh = sm + buf * PV_STG + ar * PSTR + ac;
        #pragma unroll
        for (int half = 0; half < 2; half++) {
            int o = half * 8;
            *reinterpret_cast<uint4*>(dh + o) = make_uint4(
                pack2(hh[o + 0], hh[o + 1]), pack2(hh[o + 2], hh[o + 3]),
                pack2(hh[o + 4], hh[o + 5]), pack2(hh[o + 6], hh[o + 7]));
            *reinterpret_cast<uint4*>(dh + P_SZ + o) = make_uint4(
                pack2(ll[o + 0], ll[o + 1]), pack2(ll[o + 2], ll[o + 3]),
                pack2(ll[o + 4], ll[o + 5]), pack2(ll[o + 6], ll[o + 7]));
        }
    };

    float acc[2][4][4];
    #pragma unroll
    for (int mt = 0; mt < 2; mt++)
        #pragma unroll
        for (int nt = 0; nt < 4; nt++)
            #pragma unroll
            for (int i = 0; i < 4; i++)
                acc[mt][nt][i] = 0.0f;

    auto compute = [&](int buf) {
        uint32_t s0 = sbase + (uint32_t)(buf * PV_STG) * 2;
        #pragma unroll
        for (int ks = 0; ks < 2; ks++) {
            uint32_t wh[2][4], wl[2][4];
            #pragma unroll
            for (int mt = 0; mt < 2; mt++) {
                int r = wm * 32 + mt * 16 + (lane & 15), c = ks * 16 + ((lane >> 4) << 3);
                ldmx4(wh[mt][0], wh[mt][1], wh[mt][2], wh[mt][3], s0 + (uint32_t)(r * PSTR + c) * 2);
                ldmx4(wl[mt][0], wl[mt][1], wl[mt][2], wl[mt][3], s0 + (uint32_t)(P_SZ + r * PSTR + c) * 2);
            }
            uint32_t bv[4][2];
            #pragma unroll
            for (int p = 0; p < 2; p++) {
                int kr = ks * 16 + (lane & 7) + ((lane >> 4) << 3);
                int nc = wn * 32 + p * 16 + (((lane >> 3) & 1) << 3);
                uint32_t r0, r1, r2, r3;
                ldmx4t(r0, r1, r2, r3, s0 + (uint32_t)(2 * P_SZ + kr * VSTR + nc) * 2);
                bv[2 * p][0] = r0; bv[2 * p][1] = r2; bv[2 * p + 1][0] = r1; bv[2 * p + 1][1] = r3;
            }
            #pragma unroll
            for (int mt = 0; mt < 2; mt++)
                #pragma unroll
                for (int nt = 0; nt < 4; nt++)
                    mma16816(acc[mt][nt], wh[mt][0], wh[mt][1], wh[mt][2], wh[mt][3], bv[nt][0], bv[nt][1]);
            #pragma unroll
            for (int mt = 0; mt < 2; mt++)
                #pragma unroll
                for (int nt = 0; nt < 4; nt++)
                    mma16816(acc[mt][nt], wl[mt][0], wl[mt][1], wl[mt][2], wl[mt][3], bv[nt][0], bv[nt][1]);
            #pragma unroll
            for (int p = 0; p < 2; p++) {
                int kr = ks * 16 + (lane & 7) + ((lane >> 4) << 3);
                int nc = wn * 32 + p * 16 + (((lane >> 3) & 1) << 3);
                uint32_t r0, r1, r2, r3;
                ldmx4t(r0, r1, r2, r3, s0 + (uint32_t)(2 * P_SZ + V_SZ + kr * VSTR + nc) * 2);
                bv[2 * p][0] = r0; bv[2 * p][1] = r2; bv[2 * p + 1][0] = r1; bv[2 * p + 1][1] = r3;
            }
            #pragma unroll
            for (int mt = 0; mt < 2; mt++)
                #pragma unroll
                for (int nt = 0; nt < 4; nt++)
                    mma16816(acc[mt][nt], wh[mt][0], wh[mt][1], wh[mt][2], wh[mt][3], bv[nt][0], bv[nt][1]);
        }
    };

    loadE(0);
    cpaV(0, 0);
    storeA(0, 0);
    constexpr int NKI = SEQ / 32;
    for (int t = 0; t < NKI; t++) {
        int nb = (t + 1) & 1;
        if (t + 1 < NKI) { loadE((t + 1) * 32); cpaV((t + 1) * 32, nb); CP_WAIT1(); }
        else             { CP_WAIT0(); }
        __syncthreads();
        compute(t & 1);
        if (t + 1 < NKI) storeA((t + 1) * 32, nb);
        __syncthreads();
    }

    // epilogue: split context to bf16 hi/lo
    bf16* Chz = Coh + zo * BG_STRIDE + (long long)zi * HDIM;
    bf16* Clz = Col + zo * BG_STRIDE + (long long)zi * HDIM;
    #pragma unroll
    for (int mt = 0; mt < 2; mt++) {
        int r = row0 + wm * 32 + mt * 16 + (lane >> 2);
        #pragma unroll
        for (int nt = 0; nt < 4; nt++) {
            int c = wn * 32 + nt * 8 + ((lane & 3) << 1);
            ushortT h0, l0, h1, l1, h2, l2, h3, l3;
            bsplit(acc[mt][nt][0], h0, l0); bsplit(acc[mt][nt][1], h1, l1);
            bsplit(acc[mt][nt][2], h2, l2); bsplit(acc[mt][nt][3], h3, l3);
            *reinterpret_cast<uint32_t*>(Chz + (long long)r * CH + c)       = pack2(h0, h1);
            *reinterpret_cast<uint32_t*>(Clz + (long long)r * CH + c)       = pack2(l0, l1);
            *reinterpret_cast<uint32_t*>(Chz + (long long)(r + 8) * CH + c) = pack2(h2, h3);
            *reinterpret_cast<uint32_t*>(Clz + (long long)(r + 8) * CH + c) = pack2(l2, l3);
        }
    }
}

// ---------------------------------------------------------------------------
// Launch
// ---------------------------------------------------------------------------
extern "C" void kernel_launch(void* const* d_in, const int* in_sizes, int n_in,
                              void* d_out, int out_size)
{
    const float* xq  = (const float*)d_in[0];
    const float* xkv = (const float*)d_in[1];
    const float* Wq  = (const float*)d_in[2];
    const float* bq  = (const float*)d_in[3];
    const float* Wk  = (const float*)d_in[4];
    const float* bk  = (const float*)d_in[5];
    const float* Wv  = (const float*)d_in[6];
    const float* bv  = (const float*)d_in[7];
    const float* Wo  = (const float*)d_in[8];
    const float* bo  = (const float*)d_in[9];

    float* out   = (float*)d_out;
    float* probs = out + (long long)ROWS * CH;

    bf16 *Xqh, *Xql, *Xkh, *Xkl, *Wqh, *Wql, *Wkh, *Wkl, *Wvh, *Wvl, *Woh, *Wol;
    bf16 *Qh, *Ql, *Kh, *Kl, *Vh, *Vl, *Ch, *Cl;
    float* rsum;
    cudaGetSymbolAddress((void**)&Xqh, g_Xqh); cudaGetSymbolAddress((void**)&Xql, g_Xql);
    cudaGetSymbolAddress((void**)&Xkh, g_Xkh); cudaGetSymbolAddress((void**)&Xkl, g_Xkl);
    cudaGetSymbolAddress((void**)&Wqh, g_Wqh); cudaGetSymbolAddress((void**)&Wql, g_Wql);
    cudaGetSymbolAddress((void**)&Wkh, g_Wkh); cudaGetSymbolAddress((void**)&Wkl, g_Wkl);
    cudaGetSymbolAddress((void**)&Wvh, g_Wvh); cudaGetSymbolAddress((void**)&Wvl, g_Wvl);
    cudaGetSymbolAddress((void**)&Woh, g_Woh); cudaGetSymbolAddress((void**)&Wol, g_Wol);
    cudaGetSymbolAddress((void**)&Qh, g_Qh);   cudaGetSymbolAddress((void**)&Ql, g_Ql);
    cudaGetSymbolAddress((void**)&Kh, g_Kh);   cudaGetSymbolAddress((void**)&Kl, g_Kl);
    cudaGetSymbolAddress((void**)&Vh, g_Vh);   cudaGetSymbolAddress((void**)&Vl, g_Vl);
    cudaGetSymbolAddress((void**)&Ch, g_Ch);   cudaGetSymbolAddress((void**)&Cl, g_Cl);
    cudaGetSymbolAddress((void**)&rsum, g_rowsum);

    cudaFuncSetAttribute((const void*)proj_kernel,  cudaFuncAttributeMaxDynamicSharedMemorySize, SM_DENSE);
    cudaFuncSetAttribute((const void*)out_kernel,   cudaFuncAttributeMaxDynamicSharedMemorySize, SM_DENSE);
    cudaFuncSetAttribute((const void*)score_kernel, cudaFuncAttributeMaxDynamicSharedMemorySize, SM_DENSE);
    cudaFuncSetAttribute((const void*)pv_kernel,    cudaFuncAttributeMaxDynamicSharedMemorySize, SM_PV);

    // 0. zero rowsums + split inputs/weights to bf16 hi/lo
    zero_kernel<<<BG * HEADS, SEQ>>>(rsum);
    split_kernel<<<ROWS * CH / 1024, 256>>>(xq,  Xqh, Xql);
    split_kernel<<<ROWS * CH / 1024, 256>>>(xkv, Xkh, Xkl);
    split_kernel<<<CH * CH / 1024, 256>>>(Wq, Wqh, Wql);
    split_kernel<<<CH * CH / 1024, 256>>>(Wk, Wkh, Wkl);
    split_kernel<<<CH * CH / 1024, 256>>>(Wv, Wvh, Wvl);
    split_kernel<<<CH * CH / 1024, 256>>>(Wo, Woh, Wol);

    // 1. fused Q/K/V projections (grid.z = 3)
    ProjArgs pa;
    pa.Ah[0] = Xqh; pa.Al[0] = Xql; pa.Bh[0] = Wqh; pa.Bl[0] = Wql; pa.Ch[0] = Qh; pa.Cl[0] = Ql; pa.bias[0] = bq;
    pa.Ah[1] = Xkh; pa.Al[1] = Xkl; pa.Bh[1] = Wkh; pa.Bl[1] = Wkl; pa.Ch[1] = Kh; pa.Cl[1] = Kl; pa.bias[1] = bk;
    pa.Ah[2] = Xkh; pa.Al[2] = Xkl; pa.Bh[2] = Wvh; pa.Bl[2] = Wvl; pa.Ch[2] = Vh; pa.Cl[2] = Vl; pa.bias[2] = bv;
    proj_kernel<<<dim3(CH / 128, ROWS / 128, 3), 256, SM_DENSE>>>(pa);

    // 2. scores: E = exp(s/8) + row sums
    score_kernel<<<dim3(SEQ / 128, SEQ / 128, BG * HEADS), 256, SM_DENSE>>>(Qh, Ql, Kh, Kl, probs, rsum);

    // 3. PV: normalize probs in place + context (bf16 hi/lo)
    pv_kernel<<<dim3(1, SEQ / 128, BG * HEADS), 256, SM_PV>>>(probs, Vh, Vl, rsum, Ch, Cl);

    // 4. output projection (fp32 out)
    out_kernel<<<dim3(CH / 128, ROWS / 128, 1), 256, SM_DENSE>>>(Ch, Cl, Woh, Wol, out, bo);
}